// round 12
// baseline (speedup 1.0000x reference)
#include <cuda_runtime.h>
#include <cuda_bf16.h>
#include <cstdint>

#define N 1024
#define D 2048
#define PARTS 8
#define SEGS 9
#define KDIM (SEGS*D)           // 18432
#define KSPLIT 4
#define KCHUNK (KDIM/KSPLIT)    // 4608
#define TILE 128
#define NTILES (N/TILE)         // 8
#define NPAIRS 36
#define MARGIN 0.3f

#define BKG 64                  // K elems per block (=> 128B rows, SW128 atom)
#define KB_PER_TILE (KDIM/BKG)  // 288
#define GK_ITERS (KCHUNK/BKG)   // 72 stages per CTA (divisible by STAGES)
#define STAGES 6
#define TILE_B 16384            // one 128x64 bf16 block
#define STAGE_B (2*TILE_B)      // A + B per stage
#define GEMM_THREADS 288        // 8 compute warps + 1 producer warp

// Scratch: R packed bf16 (tile-blocked, pre-swizzled), K-split partial S, mining results.
__device__ __align__(1024) __nv_bfloat16 g_R[(size_t)N * KDIM]; // 36 MB
__device__ float g_S[KSPLIT][(size_t)N * N];                    // 16 MB
__device__ float g_ap[N];
__device__ float g_an[N];
__device__ int   g_ticket;     // zero-init; reset by last mine block each launch

// ---------------------------------------------------------------------------
// PTX helpers (all sm_90-level: no 'a'-suffix features)
// ---------------------------------------------------------------------------
__device__ __forceinline__ uint32_t smem_u32(const void* p) {
    return (uint32_t)__cvta_generic_to_shared(p);
}

__device__ __forceinline__ void bulkcp(uint32_t smem, const void* g, uint32_t bytes, uint32_t mbar) {
    asm volatile(
        "cp.async.bulk.shared::cta.global.mbarrier::complete_tx::bytes [%0], [%1], %2, [%3];"
        :: "r"(smem), "l"(g), "r"(bytes), "r"(mbar) : "memory");
}
__device__ __forceinline__ void mbar_init(uint32_t m, uint32_t cnt) {
    asm volatile("mbarrier.init.shared.b64 [%0], %1;" :: "r"(m), "r"(cnt) : "memory");
}
__device__ __forceinline__ void mbar_expect_tx(uint32_t m, uint32_t bytes) {
    asm volatile("mbarrier.arrive.expect_tx.shared.b64 _, [%0], %1;" :: "r"(m), "r"(bytes) : "memory");
}
__device__ __forceinline__ void mbar_arrive(uint32_t m) {
    asm volatile("mbarrier.arrive.shared.b64 _, [%0];" :: "r"(m) : "memory");
}
__device__ __forceinline__ void mbar_wait(uint32_t m, uint32_t parity) {
    uint32_t done;
    asm volatile(
        "{\n\t.reg .pred p;\n\t"
        "mbarrier.try_wait.parity.acquire.cta.shared::cta.b64 p, [%1], %2;\n\t"
        "selp.b32 %0, 1, 0, p;\n\t}"
        : "=r"(done) : "r"(m), "r"(parity) : "memory");
    while (!done) {
        asm volatile(
            "{\n\t.reg .pred p;\n\t"
            "mbarrier.try_wait.parity.acquire.cta.shared::cta.b64 p, [%1], %2, 0x989680;\n\t"
            "selp.b32 %0, 1, 0, p;\n\t}"
            : "=r"(done) : "r"(m), "r"(parity) : "memory");
    }
}
#define FENCE_PROXY_ASYNC() asm volatile("fence.proxy.async.shared::cta;" ::: "memory")

__device__ __forceinline__ void ldm4(uint32_t* r, uint32_t addr) {
    asm volatile("ldmatrix.sync.aligned.m8n8.x4.shared.b16 {%0,%1,%2,%3}, [%4];\n"
                 : "=r"(r[0]), "=r"(r[1]), "=r"(r[2]), "=r"(r[3]) : "r"(addr));
}
__device__ __forceinline__ void mma16816(float* c, const uint32_t* a, uint32_t b0, uint32_t b1) {
    asm volatile(
        "mma.sync.aligned.m16n8k16.row.col.f32.bf16.bf16.f32 "
        "{%0,%1,%2,%3}, {%4,%5,%6,%7}, {%8,%9}, {%0,%1,%2,%3};\n"
        : "+f"(c[0]), "+f"(c[1]), "+f"(c[2]), "+f"(c[3])
        : "r"(a[0]), "r"(a[1]), "r"(a[2]), "r"(a[3]), "r"(b0), "r"(b1));
}

__device__ __forceinline__ uint32_t bf162_bits(__nv_bfloat162 v) {
    union { __nv_bfloat162 h; uint32_t u; } cvt;
    cvt.h = v;
    return cvt.u;
}

// ---------------------------------------------------------------------------
// K1: normalize/scale and pack into tile-blocked, pre-SW128-swizzled layout.
// Block (tile=row/128, kb=K/64) is 16KB: 128 rows x 128B. Within a block,
// byte (r, c[bf16]) lands at  (r*128 + c*2) ^ (((r*128+c*2)>>3)&0x70).
// Swizzle permutes 16B granules only, so 8B stores at 8B-aligned offsets stay
// contiguous (colstart multiple of 4 => byte offset multiple of 8).
// ---------------------------------------------------------------------------
__global__ void pack_kernel(const float* __restrict__ gfeat,
                            const float* __restrict__ pfeat,
                            const float* __restrict__ plab) {
    int blk = blockIdx.x;            // 0 .. N*SEGS-1
    int i   = blk / SEGS;
    int seg = blk % SEGS;
    const float* src;
    float lab = 1.0f;
    if (seg == 0) {
        src = gfeat + (size_t)i * D;
    } else {
        src = pfeat + ((size_t)i * PARTS + (seg - 1)) * D;
        lab = plab[i * PARTS + (seg - 1)];
    }
    int t = threadIdx.x;             // 256 threads, 8 floats each
    const float4* s4 = (const float4*)src;
    float4 v0 = s4[t];
    float4 v1 = s4[t + 256];
    float ss = v0.x*v0.x + v0.y*v0.y + v0.z*v0.z + v0.w*v0.w
             + v1.x*v1.x + v1.y*v1.y + v1.z*v1.z + v1.w*v1.w;
    #pragma unroll
    for (int o = 16; o > 0; o >>= 1) ss += __shfl_xor_sync(0xffffffffu, ss, o);
    __shared__ float warp_ss[8];
    __shared__ float total;
    if ((t & 31) == 0) warp_ss[t >> 5] = ss;
    __syncthreads();
    if (t == 0) {
        float s = 0.f;
        #pragma unroll
        for (int w = 0; w < 8; w++) s += warp_ss[w];
        total = s;
    }
    __syncthreads();
    float scale = lab / (sqrtf(total) + 1e-12f);

    int tile = i >> 7;
    int r    = i & 127;
    char* Rb = (char*)g_R;

    auto put8 = [&](int colstart, float4 v) {   // colstart multiple of 4 (bf16 cols)
        int c0  = seg * D + colstart;
        int kbg = c0 >> 6;
        int c   = c0 & 63;
        uint32_t inner = (uint32_t)r * 128 + (uint32_t)c * 2;
        inner ^= ((inner >> 3) & 0x70);
        uint2 val;
        val.x = bf162_bits(__float22bfloat162_rn(make_float2(v.x * scale, v.y * scale)));
        val.y = bf162_bits(__float22bfloat162_rn(make_float2(v.z * scale, v.w * scale)));
        *(uint2*)(Rb + (size_t)(tile * KB_PER_TILE + kbg) * TILE_B + inner) = val;
    };
    put8(4 * t,         v0);
    put8(4 * (t + 256), v1);
}

// ---------------------------------------------------------------------------
// K2: S = R R^T. Warp-specialized: warp 8 = producer (cp.async.bulk, 2 x 16KB
// per stage), warps 0-7 = consumers (mma.sync m16n8k16, warp tile 64x32).
// full[s]: tx-barrier (loads done). cons[s]: arrive-count 8 (all warps done
// reading slot s). No __syncthreads in the mainloop.
// 36 upper-triangle pairs x 4 K-splits = 144 CTAs (one wave).
// ---------------------------------------------------------------------------
__global__ __launch_bounds__(GEMM_THREADS, 1)
void gemm_kernel() {
    extern __shared__ char dsm[];
    __shared__ __align__(8) unsigned long long bar_full[STAGES];
    __shared__ __align__(8) unsigned long long bar_cons[STAGES];

    uint32_t sbase = (smem_u32(dsm) + 1023u) & ~1023u;

    int tid  = threadIdx.x;
    int lane = tid & 31;
    int warp = tid >> 5;

    int tileid = blockIdx.x % NPAIRS;
    int chunk  = blockIdx.x / NPAIRS;
    int bi = 0, tt = tileid;
    while (tt >= NTILES - bi) { tt -= NTILES - bi; bi++; }
    int bj = bi + tt;

    const char* Rb = (const char*)g_R;
    size_t abase = ((size_t)bi * KB_PER_TILE + (size_t)chunk * GK_ITERS) * TILE_B;
    size_t bbase = ((size_t)bj * KB_PER_TILE + (size_t)chunk * GK_ITERS) * TILE_B;

    if (tid == 0) {
        #pragma unroll
        for (int s = 0; s < STAGES; s++) {
            mbar_init(smem_u32(&bar_full[s]), 1);
            mbar_init(smem_u32(&bar_cons[s]), 8);
        }
        FENCE_PROXY_ASYNC();
    }
    __syncthreads();

    if (warp == 8) {
        // ---------------- producer ----------------
        if (lane == 0) {
            #pragma unroll
            for (int s = 0; s < STAGES; s++) {          // prologue: fill ring
                uint32_t sb = sbase + s * STAGE_B;
                uint32_t fb = smem_u32(&bar_full[s]);
                mbar_expect_tx(fb, STAGE_B);
                bulkcp(sb,          Rb + abase + (size_t)s * TILE_B, TILE_B, fb);
                bulkcp(sb + TILE_B, Rb + bbase + (size_t)s * TILE_B, TILE_B, fb);
            }
            for (int base = STAGES; base < GK_ITERS; base += STAGES) {
                int phase = ((base / STAGES) - 1) & 1;
                #pragma unroll
                for (int s = 0; s < STAGES; s++) {
                    mbar_wait(smem_u32(&bar_cons[s]), phase);
                    int ld = base + s;
                    uint32_t sb = sbase + s * STAGE_B;
                    uint32_t fb = smem_u32(&bar_full[s]);
                    mbar_expect_tx(fb, STAGE_B);
                    bulkcp(sb,          Rb + abase + (size_t)ld * TILE_B, TILE_B, fb);
                    bulkcp(sb + TILE_B, Rb + bbase + (size_t)ld * TILE_B, TILE_B, fb);
                }
            }
        }
        return;
    }

    // ---------------- consumers (warps 0-7) ----------------
    int wm = warp >> 2;      // 0..1
    int wn = warp & 3;       // 0..3

    float acc[4][4][4];
    #pragma unroll
    for (int mi = 0; mi < 4; mi++)
        #pragma unroll
        for (int ni = 0; ni < 4; ni++)
            #pragma unroll
            for (int e = 0; e < 4; e++) acc[mi][ni][e] = 0.f;

    for (int base = 0; base < GK_ITERS; base += STAGES) {
        int phase = (base / STAGES) & 1;
        #pragma unroll
        for (int s = 0; s < STAGES; s++) {
            mbar_wait(smem_u32(&bar_full[s]), phase);
            uint32_t stA = sbase + s * STAGE_B;
            uint32_t stB = stA + TILE_B;

            #pragma unroll
            for (int ks = 0; ks < BKG; ks += 16) {
                uint32_t af[4][4];
                #pragma unroll
                for (int mi = 0; mi < 4; mi++) {
                    int r = wm * 64 + mi * 16 + (lane & 15);
                    int g = (ks >> 3) + (lane >> 4);
                    ldm4(af[mi], stA + r * 128 + ((g ^ (r & 7)) << 4));
                }
                uint32_t bfr[2][4];
                #pragma unroll
                for (int nb = 0; nb < 2; nb++) {
                    int g8 = lane >> 3;
                    int r  = wn * 32 + nb * 16 + ((g8 & 2) ? 8 : 0) + (lane & 7);
                    int g  = (ks >> 3) + (g8 & 1);
                    ldm4(bfr[nb], stB + r * 128 + ((g ^ (r & 7)) << 4));
                }
                #pragma unroll
                for (int mi = 0; mi < 4; mi++)
                    #pragma unroll
                    for (int ni = 0; ni < 4; ni++)
                        mma16816(acc[mi][ni], af[mi],
                                 bfr[ni >> 1][(ni & 1) * 2],
                                 bfr[ni >> 1][(ni & 1) * 2 + 1]);
            }
            if (lane == 0) mbar_arrive(smem_u32(&bar_cons[s]));
        }
    }

    // Epilogue: write partial S (upper triangle region only).
    float* Sc = g_S[chunk];
    int rowbase = bi * TILE + wm * 64;
    int colbase = bj * TILE + wn * 32;
    #pragma unroll
    for (int mi = 0; mi < 4; mi++) {
        int r0 = rowbase + mi * 16 + (lane >> 2);
        #pragma unroll
        for (int ni = 0; ni < 4; ni++) {
            int c0 = colbase + ni * 8 + (lane & 3) * 2;
            *(float2*)&Sc[(size_t)r0 * N + c0]       = make_float2(acc[mi][ni][0], acc[mi][ni][1]);
            *(float2*)&Sc[(size_t)(r0 + 8) * N + c0] = make_float2(acc[mi][ni][2], acc[mi][ni][3]);
        }
    }
}

// ---------------------------------------------------------------------------
// K3 (fused mine+loss): dist_ij = 0.5 - S_ij / (2*(O_ij+1)); hardest pos/neg
// per row; last block (ticket) reduces the loss and resets the ticket.
// Runtime dtype detection for global_labels (int32 vs int64).
// ---------------------------------------------------------------------------
__global__ void mine_kernel(const float* __restrict__ plab,
                            const void* __restrict__ glab_raw,
                            float* __restrict__ out) {
    int i = blockIdx.x;
    int t = threadIdx.x;   // 128

    __shared__ int slab[N];
    __shared__ int is64_s;

    if (t == 0) {
        const unsigned* w = (const unsigned*)glab_raw;
        unsigned acc = 0;
        for (int q = 1; q < 1024; q += 2) acc |= w[q];
        is64_s = (acc == 0) ? 1 : 0;
    }
    __syncthreads();
    if (is64_s) {
        const long long* g64 = (const long long*)glab_raw;
        for (int j = t; j < N; j += 128) slab[j] = (int)g64[j];
    } else {
        const int* g32 = (const int*)glab_raw;
        for (int j = t; j < N; j += 128) slab[j] = g32[j];
    }
    __syncthreads();

    int gi = slab[i];
    float Li[8];
    #pragma unroll
    for (int p = 0; p < 8; p++) Li[p] = plab[i * 8 + p];

    float mx = -3.4e38f, mn = 3.4e38f;
    for (int j = t; j < N; j += 128) {
        size_t idx = (i <= j) ? ((size_t)i * N + j) : ((size_t)j * N + i);
        float S = g_S[0][idx] + g_S[1][idx] + g_S[2][idx] + g_S[3][idx];
        const float4* Lj4 = (const float4*)&plab[j * 8];
        float4 a = Lj4[0], b = Lj4[1];
        float O = Li[0]*a.x + Li[1]*a.y + Li[2]*a.z + Li[3]*a.w
                + Li[4]*b.x + Li[5]*b.y + Li[6]*b.z + Li[7]*b.w;
        float dist = 0.5f - S / (2.0f * (O + 1.0f));
        if (slab[j] == gi) mx = fmaxf(mx, dist);
        else               mn = fminf(mn, dist);
    }
    #pragma unroll
    for (int o = 16; o > 0; o >>= 1) {
        mx = fmaxf(mx, __shfl_xor_sync(0xffffffffu, mx, o));
        mn = fminf(mn, __shfl_xor_sync(0xffffffffu, mn, o));
    }
    __shared__ float smx[4], smn[4];
    __shared__ int   last_s;
    if ((t & 31) == 0) { smx[t >> 5] = mx; smn[t >> 5] = mn; }
    __syncthreads();
    if (t == 0) {
        #pragma unroll
        for (int w = 1; w < 4; w++) {
            smx[0] = fmaxf(smx[0], smx[w]);
            smn[0] = fminf(smn[0], smn[w]);
        }
        g_ap[i] = smx[0];
        g_an[i] = smn[0];
        __threadfence();
        last_s = (atomicAdd(&g_ticket, 1) == N - 1);
    }
    __syncthreads();
    if (last_s) {
        float s = 0.f;
        for (int j = t; j < N; j += 128)
            s += fmaxf(g_ap[j] - g_an[j] + MARGIN, 0.f);
        #pragma unroll
        for (int o = 16; o > 0; o >>= 1) s += __shfl_xor_sync(0xffffffffu, s, o);
        __shared__ float ws[4];
        if ((t & 31) == 0) ws[t >> 5] = s;
        __syncthreads();
        if (t == 0) {
            float tot = ws[0] + ws[1] + ws[2] + ws[3];
            out[0] = tot / (float)N;
            g_ticket = 0;            // reset for next (graph-replayed) launch
        }
    }
}

// ---------------------------------------------------------------------------
extern "C" void kernel_launch(void* const* d_in, const int* in_sizes, int n_in,
                              void* d_out, int out_size) {
    const float* gfeat = (const float*)d_in[0];      // [1024, 2048]
    const float* pfeat = (const float*)d_in[1];      // [1024, 8, 2048]
    const float* plab  = (const float*)d_in[2];      // [1024, 8]
    const void*  glab  = d_in[3];                    // [1024] int32 or int64

    static bool attr_set = false;
    if (!attr_set) {
        cudaFuncSetAttribute(gemm_kernel,
                             cudaFuncAttributeMaxDynamicSharedMemorySize,
                             STAGES * STAGE_B + 1024);
        attr_set = true;
    }

    pack_kernel<<<N * SEGS, 256>>>(gfeat, pfeat, plab);
    gemm_kernel<<<NPAIRS * KSPLIT, GEMM_THREADS, STAGES * STAGE_B + 1024>>>();
    mine_kernel<<<N, 128>>>(plab, glab, (float*)d_out);
}

// round 13
// speedup vs baseline: 1.3435x; 1.3435x over previous
#include <cuda_runtime.h>
#include <cuda_bf16.h>
#include <cstdint>

#define N 1024
#define D 2048
#define PARTS 8
#define SEGS 9
#define KDIM (SEGS*D)           // 18432
#define KSPLIT 4
#define KCHUNK (KDIM/KSPLIT)    // 4608
#define TILE 128
#define NTILES (N/TILE)         // 8
#define NPAIRS 36
#define MARGIN 0.3f

#define BKG 64                  // K elems per block (=> 128B rows, SW128 atom)
#define KB_PER_TILE (KDIM/BKG)  // 288
#define GK_ITERS (KCHUNK/BKG)   // 72 stages per CTA (even, divisible by STAGES)
#define STAGES 6
#define TILE_B 16384            // one 128x64 bf16 block
#define STAGE_B (2*TILE_B)      // A + B per stage

// Scratch: R packed bf16 (tile-blocked, pre-swizzled), K-split partial S, mining results.
__device__ __align__(1024) __nv_bfloat16 g_R[(size_t)N * KDIM]; // 36 MB
__device__ float g_S[KSPLIT][(size_t)N * N];                    // 16 MB
__device__ float g_ap[N];
__device__ float g_an[N];
__device__ int   g_ticket;     // zero-init; reset by last mine block each launch

// ---------------------------------------------------------------------------
// PTX helpers (all sm_90-level: no 'a'-suffix features)
// ---------------------------------------------------------------------------
__device__ __forceinline__ uint32_t smem_u32(const void* p) {
    return (uint32_t)__cvta_generic_to_shared(p);
}

__device__ __forceinline__ void bulkcp(uint32_t smem, const void* g, uint32_t bytes, uint32_t mbar) {
    asm volatile(
        "cp.async.bulk.shared::cta.global.mbarrier::complete_tx::bytes [%0], [%1], %2, [%3];"
        :: "r"(smem), "l"(g), "r"(bytes), "r"(mbar) : "memory");
}
__device__ __forceinline__ void mbar_init(uint32_t m, uint32_t cnt) {
    asm volatile("mbarrier.init.shared.b64 [%0], %1;" :: "r"(m), "r"(cnt) : "memory");
}
__device__ __forceinline__ void mbar_expect_tx(uint32_t m, uint32_t bytes) {
    asm volatile("mbarrier.arrive.expect_tx.shared.b64 _, [%0], %1;" :: "r"(m), "r"(bytes) : "memory");
}
__device__ __forceinline__ void mbar_wait(uint32_t m, uint32_t parity) {
    uint32_t done;
    asm volatile(
        "{\n\t.reg .pred p;\n\t"
        "mbarrier.try_wait.parity.acquire.cta.shared::cta.b64 p, [%1], %2;\n\t"
        "selp.b32 %0, 1, 0, p;\n\t}"
        : "=r"(done) : "r"(m), "r"(parity) : "memory");
    while (!done) {
        asm volatile(
            "{\n\t.reg .pred p;\n\t"
            "mbarrier.try_wait.parity.acquire.cta.shared::cta.b64 p, [%1], %2, 0x989680;\n\t"
            "selp.b32 %0, 1, 0, p;\n\t}"
            : "=r"(done) : "r"(m), "r"(parity) : "memory");
    }
}
#define FENCE_PROXY_ASYNC() asm volatile("fence.proxy.async.shared::cta;" ::: "memory")

__device__ __forceinline__ void ldm4(uint32_t* r, uint32_t addr) {
    asm volatile("ldmatrix.sync.aligned.m8n8.x4.shared.b16 {%0,%1,%2,%3}, [%4];\n"
                 : "=r"(r[0]), "=r"(r[1]), "=r"(r[2]), "=r"(r[3]) : "r"(addr));
}
__device__ __forceinline__ void mma16816(float* c, const uint32_t* a, uint32_t b0, uint32_t b1) {
    asm volatile(
        "mma.sync.aligned.m16n8k16.row.col.f32.bf16.bf16.f32 "
        "{%0,%1,%2,%3}, {%4,%5,%6,%7}, {%8,%9}, {%0,%1,%2,%3};\n"
        : "+f"(c[0]), "+f"(c[1]), "+f"(c[2]), "+f"(c[3])
        : "r"(a[0]), "r"(a[1]), "r"(a[2]), "r"(a[3]), "r"(b0), "r"(b1));
}

// ---------------------------------------------------------------------------
// K1: normalize/scale and pack into tile-blocked, pre-SW128-swizzled layout.
// (Exact R10 version — proven 19.6us at 54.8% DRAM.)
// ---------------------------------------------------------------------------
__global__ void pack_kernel(const float* __restrict__ gfeat,
                            const float* __restrict__ pfeat,
                            const float* __restrict__ plab) {
    int blk = blockIdx.x;            // 0 .. N*SEGS-1
    int i   = blk / SEGS;
    int seg = blk % SEGS;
    const float* src;
    float lab = 1.0f;
    if (seg == 0) {
        src = gfeat + (size_t)i * D;
    } else {
        src = pfeat + ((size_t)i * PARTS + (seg - 1)) * D;
        lab = plab[i * PARTS + (seg - 1)];
    }
    int t = threadIdx.x;             // 256 threads, 8 floats each
    const float4* s4 = (const float4*)src;
    float4 v0 = s4[t];
    float4 v1 = s4[t + 256];
    float ss = v0.x*v0.x + v0.y*v0.y + v0.z*v0.z + v0.w*v0.w
             + v1.x*v1.x + v1.y*v1.y + v1.z*v1.z + v1.w*v1.w;
    #pragma unroll
    for (int o = 16; o > 0; o >>= 1) ss += __shfl_xor_sync(0xffffffffu, ss, o);
    __shared__ float warp_ss[8];
    __shared__ float total;
    if ((t & 31) == 0) warp_ss[t >> 5] = ss;
    __syncthreads();
    if (t == 0) {
        float s = 0.f;
        #pragma unroll
        for (int w = 0; w < 8; w++) s += warp_ss[w];
        total = s;
    }
    __syncthreads();
    float scale = lab / (sqrtf(total) + 1e-12f);

    int tile = i >> 7;
    int r    = i & 127;
    char* Rb = (char*)g_R;

    auto put = [&](int P, float a, float b) {   // P = bf16-pair index within row segment
        int c0  = seg * D + 2 * P;              // global K column (even)
        int kbg = c0 >> 6;
        int c   = c0 & 63;
        uint32_t inner = (uint32_t)r * 128 + (uint32_t)c * 2;
        inner ^= ((inner >> 3) & 0x70);         // SW128 pre-swizzle
        __nv_bfloat162 v = __float22bfloat162_rn(make_float2(a, b));
        *(__nv_bfloat162*)(Rb + (size_t)(tile * KB_PER_TILE + kbg) * TILE_B + inner) = v;
    };
    put(2*t,           v0.x*scale, v0.y*scale);
    put(2*t+1,         v0.z*scale, v0.w*scale);
    put(2*(t+256),     v1.x*scale, v1.y*scale);
    put(2*(t+256)+1,   v1.z*scale, v1.w*scale);
}

// ---------------------------------------------------------------------------
// K2: S = R R^T. cp.async.bulk (2 x 16KB per stage, single thread) feeds a
// 6-stage mbarrier ring; 8 warps of mma.sync m16n8k16 consume (warp tile 64x32).
// Stages processed in PAIRS: one __syncthreads per two stages (halved barrier
// count vs R10), then both freed slots are refilled.
// 36 upper-triangle pairs x 4 K-splits = 144 CTAs (one wave).
// ---------------------------------------------------------------------------
__global__ __launch_bounds__(256, 1)
void gemm_kernel() {
    extern __shared__ char dsm[];
    __shared__ __align__(8) unsigned long long bar_full[STAGES];

    uint32_t sbase = (smem_u32(dsm) + 1023u) & ~1023u;

    int tid  = threadIdx.x;
    int lane = tid & 31;
    int warp = tid >> 5;
    int wm   = warp >> 2;    // 0..1
    int wn   = warp & 3;     // 0..3

    int tileid = blockIdx.x % NPAIRS;
    int chunk  = blockIdx.x / NPAIRS;
    int bi = 0, tt = tileid;
    while (tt >= NTILES - bi) { tt -= NTILES - bi; bi++; }
    int bj = bi + tt;

    const char* Rb = (const char*)g_R;
    size_t abase = ((size_t)bi * KB_PER_TILE + (size_t)chunk * GK_ITERS) * TILE_B;
    size_t bbase = ((size_t)bj * KB_PER_TILE + (size_t)chunk * GK_ITERS) * TILE_B;

    if (tid == 0) {
        #pragma unroll
        for (int s = 0; s < STAGES; s++) mbar_init(smem_u32(&bar_full[s]), 1);
        FENCE_PROXY_ASYNC();
    }
    __syncthreads();

    if (tid == 0) {
        #pragma unroll
        for (int s = 0; s < STAGES; s++) {     // prologue: fill all stages
            uint32_t sb = sbase + s * STAGE_B;
            uint32_t fb = smem_u32(&bar_full[s]);
            mbar_expect_tx(fb, STAGE_B);
            bulkcp(sb,          Rb + abase + (size_t)s * TILE_B, TILE_B, fb);
            bulkcp(sb + TILE_B, Rb + bbase + (size_t)s * TILE_B, TILE_B, fb);
        }
    }

    float acc[4][4][4];
    #pragma unroll
    for (int mi = 0; mi < 4; mi++)
        #pragma unroll
        for (int ni = 0; ni < 4; ni++)
            #pragma unroll
            for (int e = 0; e < 4; e++) acc[mi][ni][e] = 0.f;

    auto compute_stage = [&](int s, int phase) {
        mbar_wait(smem_u32(&bar_full[s]), phase);
        uint32_t stA = sbase + s * STAGE_B;
        uint32_t stB = stA + TILE_B;
        #pragma unroll
        for (int ks = 0; ks < BKG; ks += 16) {
            uint32_t af[4][4];
            #pragma unroll
            for (int mi = 0; mi < 4; mi++) {
                int r = wm * 64 + mi * 16 + (lane & 15);
                int g = (ks >> 3) + (lane >> 4);
                ldm4(af[mi], stA + r * 128 + ((g ^ (r & 7)) << 4));
            }
            uint32_t bfr[2][4];
            #pragma unroll
            for (int nb = 0; nb < 2; nb++) {
                int g8 = lane >> 3;
                int r  = wn * 32 + nb * 16 + ((g8 & 2) ? 8 : 0) + (lane & 7);
                int g  = (ks >> 3) + (g8 & 1);
                ldm4(bfr[nb], stB + r * 128 + ((g ^ (r & 7)) << 4));
            }
            #pragma unroll
            for (int mi = 0; mi < 4; mi++)
                #pragma unroll
                for (int ni = 0; ni < 4; ni++)
                    mma16816(acc[mi][ni], af[mi],
                             bfr[ni >> 1][(ni & 1) * 2],
                             bfr[ni >> 1][(ni & 1) * 2 + 1]);
        }
    };

    for (int it = 0; it < GK_ITERS; it += 2) {
        int s0    = it % STAGES;               // even slot
        int s1    = s0 + 1;                    // odd slot, same ring trip
        int phase = (it / STAGES) & 1;

        compute_stage(s0, phase);
        compute_stage(s1, phase);

        __syncthreads();                       // all reads of slots s0,s1 done
        if (tid == 0) {                        // refill both freed slots
            #pragma unroll
            for (int q = 0; q < 2; q++) {
                int ld = it + q + STAGES;
                if (ld < GK_ITERS) {
                    int s = (q == 0) ? s0 : s1;
                    uint32_t sb = sbase + s * STAGE_B;
                    uint32_t fb = smem_u32(&bar_full[s]);
                    mbar_expect_tx(fb, STAGE_B);
                    bulkcp(sb,          Rb + abase + (size_t)ld * TILE_B, TILE_B, fb);
                    bulkcp(sb + TILE_B, Rb + bbase + (size_t)ld * TILE_B, TILE_B, fb);
                }
            }
        }
    }

    // Epilogue: write partial S (upper triangle region only).
    float* Sc = g_S[chunk];
    int rowbase = bi * TILE + wm * 64;
    int colbase = bj * TILE + wn * 32;
    #pragma unroll
    for (int mi = 0; mi < 4; mi++) {
        int r0 = rowbase + mi * 16 + (lane >> 2);
        #pragma unroll
        for (int ni = 0; ni < 4; ni++) {
            int c0 = colbase + ni * 8 + (lane & 3) * 2;
            *(float2*)&Sc[(size_t)r0 * N + c0]       = make_float2(acc[mi][ni][0], acc[mi][ni][1]);
            *(float2*)&Sc[(size_t)(r0 + 8) * N + c0] = make_float2(acc[mi][ni][2], acc[mi][ni][3]);
        }
    }
}

// ---------------------------------------------------------------------------
// K3 (fused mine+loss): dist_ij = 0.5 - S_ij / (2*(O_ij+1)); hardest pos/neg
// per row; last block (ticket) reduces the loss and resets the ticket.
// Runtime dtype detection for global_labels (int32 vs int64).
// ---------------------------------------------------------------------------
__global__ void mine_kernel(const float* __restrict__ plab,
                            const void* __restrict__ glab_raw,
                            float* __restrict__ out) {
    int i = blockIdx.x;
    int t = threadIdx.x;   // 128

    __shared__ int slab[N];
    __shared__ int is64_s;

    if (t == 0) {
        const unsigned* w = (const unsigned*)glab_raw;
        unsigned acc = 0;
        for (int q = 1; q < 1024; q += 2) acc |= w[q];
        is64_s = (acc == 0) ? 1 : 0;
    }
    __syncthreads();
    if (is64_s) {
        const long long* g64 = (const long long*)glab_raw;
        for (int j = t; j < N; j += 128) slab[j] = (int)g64[j];
    } else {
        const int* g32 = (const int*)glab_raw;
        for (int j = t; j < N; j += 128) slab[j] = g32[j];
    }
    __syncthreads();

    int gi = slab[i];
    float Li[8];
    #pragma unroll
    for (int p = 0; p < 8; p++) Li[p] = plab[i * 8 + p];

    float mx = -3.4e38f, mn = 3.4e38f;
    for (int j = t; j < N; j += 128) {
        size_t idx = (i <= j) ? ((size_t)i * N + j) : ((size_t)j * N + i);
        float S = g_S[0][idx] + g_S[1][idx] + g_S[2][idx] + g_S[3][idx];
        const float4* Lj4 = (const float4*)&plab[j * 8];
        float4 a = Lj4[0], b = Lj4[1];
        float O = Li[0]*a.x + Li[1]*a.y + Li[2]*a.z + Li[3]*a.w
                + Li[4]*b.x + Li[5]*b.y + Li[6]*b.z + Li[7]*b.w;
        float dist = 0.5f - S / (2.0f * (O + 1.0f));
        if (slab[j] == gi) mx = fmaxf(mx, dist);
        else               mn = fminf(mn, dist);
    }
    #pragma unroll
    for (int o = 16; o > 0; o >>= 1) {
        mx = fmaxf(mx, __shfl_xor_sync(0xffffffffu, mx, o));
        mn = fminf(mn, __shfl_xor_sync(0xffffffffu, mn, o));
    }
    __shared__ float smx[4], smn[4];
    __shared__ int   last_s;
    if ((t & 31) == 0) { smx[t >> 5] = mx; smn[t >> 5] = mn; }
    __syncthreads();
    if (t == 0) {
        #pragma unroll
        for (int w = 1; w < 4; w++) {
            smx[0] = fmaxf(smx[0], smx[w]);
            smn[0] = fminf(smn[0], smn[w]);
        }
        g_ap[i] = smx[0];
        g_an[i] = smn[0];
        __threadfence();
        last_s = (atomicAdd(&g_ticket, 1) == N - 1);
    }
    __syncthreads();
    if (last_s) {
        float s = 0.f;
        for (int j = t; j < N; j += 128)
            s += fmaxf(g_ap[j] - g_an[j] + MARGIN, 0.f);
        #pragma unroll
        for (int o = 16; o > 0; o >>= 1) s += __shfl_xor_sync(0xffffffffu, s, o);
        __shared__ float ws[4];
        if ((t & 31) == 0) ws[t >> 5] = s;
        __syncthreads();
        if (t == 0) {
            float tot = ws[0] + ws[1] + ws[2] + ws[3];
            out[0] = tot / (float)N;
            g_ticket = 0;            // reset for next (graph-replayed) launch
        }
    }
}

// ---------------------------------------------------------------------------
extern "C" void kernel_launch(void* const* d_in, const int* in_sizes, int n_in,
                              void* d_out, int out_size) {
    const float* gfeat = (const float*)d_in[0];      // [1024, 2048]
    const float* pfeat = (const float*)d_in[1];      // [1024, 8, 2048]
    const float* plab  = (const float*)d_in[2];      // [1024, 8]
    const void*  glab  = d_in[3];                    // [1024] int32 or int64

    static bool attr_set = false;
    if (!attr_set) {
        cudaFuncSetAttribute(gemm_kernel,
                             cudaFuncAttributeMaxDynamicSharedMemorySize,
                             STAGES * STAGE_B + 1024);
        attr_set = true;
    }

    pack_kernel<<<N * SEGS, 256>>>(gfeat, pfeat, plab);
    gemm_kernel<<<NPAIRS * KSPLIT, 256, STAGES * STAGE_B + 1024>>>();
    mine_kernel<<<N, 128>>>(plab, glab, (float*)d_out);
}

// round 16
// speedup vs baseline: 1.5621x; 1.1627x over previous
#include <cuda_runtime.h>
#include <cuda_bf16.h>
#include <cstdint>

#define N 1024
#define D 2048
#define PARTS 8
#define SEGS 9
#define KDIM (SEGS*D)           // 18432
#define KSPLIT 4
#define KCHUNK (KDIM/KSPLIT)    // 4608
#define TILE 128
#define NTILES (N/TILE)         // 8
#define NPAIRS 36
#define MARGIN 0.3f

#define BKG 64                  // K elems per block (=> 128B rows, SW128 atom)
#define KB_PER_TILE (KDIM/BKG)  // 288
#define GK_ITERS (KCHUNK/BKG)   // 72 stages per CTA (divisible by 3 and STAGES)
#define STAGES 6
#define TILE_B 16384            // one 128x64 bf16 block
#define STAGE_B (2*TILE_B)      // A + B per stage

// Scratch: R packed bf16 (tile-blocked, pre-swizzled), K-split partial S, mining results.
__device__ __align__(1024) __nv_bfloat16 g_R[(size_t)N * KDIM]; // 36 MB
__device__ float g_S[KSPLIT][(size_t)N * N];                    // 16 MB
__device__ float g_ap[N];
__device__ float g_an[N];
__device__ int   g_ticket;     // zero-init; reset by last mine block each launch

// ---------------------------------------------------------------------------
// PTX helpers (all sm_90-level: no 'a'-suffix features)
// ---------------------------------------------------------------------------
__device__ __forceinline__ uint32_t smem_u32(const void* p) {
    return (uint32_t)__cvta_generic_to_shared(p);
}

__device__ __forceinline__ void bulkcp(uint32_t smem, const void* g, uint32_t bytes, uint32_t mbar) {
    asm volatile(
        "cp.async.bulk.shared::cta.global.mbarrier::complete_tx::bytes [%0], [%1], %2, [%3];"
        :: "r"(smem), "l"(g), "r"(bytes), "r"(mbar) : "memory");
}
__device__ __forceinline__ void mbar_init(uint32_t m, uint32_t cnt) {
    asm volatile("mbarrier.init.shared.b64 [%0], %1;" :: "r"(m), "r"(cnt) : "memory");
}
__device__ __forceinline__ void mbar_expect_tx(uint32_t m, uint32_t bytes) {
    asm volatile("mbarrier.arrive.expect_tx.shared.b64 _, [%0], %1;" :: "r"(m), "r"(bytes) : "memory");
}
__device__ __forceinline__ void mbar_wait(uint32_t m, uint32_t parity) {
    uint32_t done;
    asm volatile(
        "{\n\t.reg .pred p;\n\t"
        "mbarrier.try_wait.parity.acquire.cta.shared::cta.b64 p, [%1], %2;\n\t"
        "selp.b32 %0, 1, 0, p;\n\t}"
        : "=r"(done) : "r"(m), "r"(parity) : "memory");
    while (!done) {
        asm volatile(
            "{\n\t.reg .pred p;\n\t"
            "mbarrier.try_wait.parity.acquire.cta.shared::cta.b64 p, [%1], %2, 0x989680;\n\t"
            "selp.b32 %0, 1, 0, p;\n\t}"
            : "=r"(done) : "r"(m), "r"(parity) : "memory");
    }
}
#define FENCE_PROXY_ASYNC() asm volatile("fence.proxy.async.shared::cta;" ::: "memory")

__device__ __forceinline__ void ldm4(uint32_t* r, uint32_t addr) {
    asm volatile("ldmatrix.sync.aligned.m8n8.x4.shared.b16 {%0,%1,%2,%3}, [%4];\n"
                 : "=r"(r[0]), "=r"(r[1]), "=r"(r[2]), "=r"(r[3]) : "r"(addr));
}
__device__ __forceinline__ void mma16816(float* c, const uint32_t* a, uint32_t b0, uint32_t b1) {
    asm volatile(
        "mma.sync.aligned.m16n8k16.row.col.f32.bf16.bf16.f32 "
        "{%0,%1,%2,%3}, {%4,%5,%6,%7}, {%8,%9}, {%0,%1,%2,%3};\n"
        : "+f"(c[0]), "+f"(c[1]), "+f"(c[2]), "+f"(c[3])
        : "r"(a[0]), "r"(a[1]), "r"(a[2]), "r"(a[3]), "r"(b0), "r"(b1));
}

// ---------------------------------------------------------------------------
// K1: normalize/scale and pack into tile-blocked, pre-SW128-swizzled layout.
// (Exact R10/R13 version — proven 19.4-19.6us at ~55% DRAM.)
// ---------------------------------------------------------------------------
__global__ void pack_kernel(const float* __restrict__ gfeat,
                            const float* __restrict__ pfeat,
                            const float* __restrict__ plab) {
    int blk = blockIdx.x;            // 0 .. N*SEGS-1
    int i   = blk / SEGS;
    int seg = blk % SEGS;
    const float* src;
    float lab = 1.0f;
    if (seg == 0) {
        src = gfeat + (size_t)i * D;
    } else {
        src = pfeat + ((size_t)i * PARTS + (seg - 1)) * D;
        lab = plab[i * PARTS + (seg - 1)];
    }
    int t = threadIdx.x;             // 256 threads, 8 floats each
    const float4* s4 = (const float4*)src;
    float4 v0 = s4[t];
    float4 v1 = s4[t + 256];
    float ss = v0.x*v0.x + v0.y*v0.y + v0.z*v0.z + v0.w*v0.w
             + v1.x*v1.x + v1.y*v1.y + v1.z*v1.z + v1.w*v1.w;
    #pragma unroll
    for (int o = 16; o > 0; o >>= 1) ss += __shfl_xor_sync(0xffffffffu, ss, o);
    __shared__ float warp_ss[8];
    __shared__ float total;
    if ((t & 31) == 0) warp_ss[t >> 5] = ss;
    __syncthreads();
    if (t == 0) {
        float s = 0.f;
        #pragma unroll
        for (int w = 0; w < 8; w++) s += warp_ss[w];
        total = s;
    }
    __syncthreads();
    float scale = lab / (sqrtf(total) + 1e-12f);

    int tile = i >> 7;
    int r    = i & 127;
    char* Rb = (char*)g_R;

    auto put = [&](int P, float a, float b) {   // P = bf16-pair index within row segment
        int c0  = seg * D + 2 * P;              // global K column (even)
        int kbg = c0 >> 6;
        int c   = c0 & 63;
        uint32_t inner = (uint32_t)r * 128 + (uint32_t)c * 2;
        inner ^= ((inner >> 3) & 0x70);         // SW128 pre-swizzle
        __nv_bfloat162 v = __float22bfloat162_rn(make_float2(a, b));
        *(__nv_bfloat162*)(Rb + (size_t)(tile * KB_PER_TILE + kbg) * TILE_B + inner) = v;
    };
    put(2*t,           v0.x*scale, v0.y*scale);
    put(2*t+1,         v0.z*scale, v0.w*scale);
    put(2*(t+256),     v1.x*scale, v1.y*scale);
    put(2*(t+256)+1,   v1.z*scale, v1.w*scale);
}

// ---------------------------------------------------------------------------
// K2: S = R R^T. cp.async.bulk feeds a 6-stage mbarrier ring; 8 warps of
// mma.sync m16n8k16 consume. Stages processed in TRIPLES: one __syncthreads
// per three stages (24 CTA barriers total). Epilogue writes BOTH (i,j) and
// (j,i) so S is fully materialized (mine reads become row-coalesced).
// 36 upper-triangle pairs x 4 K-splits = 144 CTAs (one wave).
// ---------------------------------------------------------------------------
__global__ __launch_bounds__(256, 1)
void gemm_kernel() {
    extern __shared__ char dsm[];
    __shared__ __align__(8) unsigned long long bar_full[STAGES];

    uint32_t sbase = (smem_u32(dsm) + 1023u) & ~1023u;

    int tid  = threadIdx.x;
    int lane = tid & 31;
    int warp = tid >> 5;
    int wm   = warp >> 2;    // 0..1
    int wn   = warp & 3;     // 0..3

    int tileid = blockIdx.x % NPAIRS;
    int chunk  = blockIdx.x / NPAIRS;
    int bi = 0, tt = tileid;
    while (tt >= NTILES - bi) { tt -= NTILES - bi; bi++; }
    int bj = bi + tt;

    const char* Rb = (const char*)g_R;
    size_t abase = ((size_t)bi * KB_PER_TILE + (size_t)chunk * GK_ITERS) * TILE_B;
    size_t bbase = ((size_t)bj * KB_PER_TILE + (size_t)chunk * GK_ITERS) * TILE_B;

    if (tid == 0) {
        #pragma unroll
        for (int s = 0; s < STAGES; s++) mbar_init(smem_u32(&bar_full[s]), 1);
        FENCE_PROXY_ASYNC();
    }
    __syncthreads();

    if (tid == 0) {
        #pragma unroll
        for (int s = 0; s < STAGES; s++) {     // prologue: fill all stages
            uint32_t sb = sbase + s * STAGE_B;
            uint32_t fb = smem_u32(&bar_full[s]);
            mbar_expect_tx(fb, STAGE_B);
            bulkcp(sb,          Rb + abase + (size_t)s * TILE_B, TILE_B, fb);
            bulkcp(sb + TILE_B, Rb + bbase + (size_t)s * TILE_B, TILE_B, fb);
        }
    }

    float acc[4][4][4];
    #pragma unroll
    for (int mi = 0; mi < 4; mi++)
        #pragma unroll
        for (int ni = 0; ni < 4; ni++)
            #pragma unroll
            for (int e = 0; e < 4; e++) acc[mi][ni][e] = 0.f;

    auto compute_stage = [&](int s, int phase) {
        mbar_wait(smem_u32(&bar_full[s]), phase);
        uint32_t stA = sbase + s * STAGE_B;
        uint32_t stB = stA + TILE_B;
        #pragma unroll
        for (int ks = 0; ks < BKG; ks += 16) {
            uint32_t af[4][4];
            #pragma unroll
            for (int mi = 0; mi < 4; mi++) {
                int r = wm * 64 + mi * 16 + (lane & 15);
                int g = (ks >> 3) + (lane >> 4);
                ldm4(af[mi], stA + r * 128 + ((g ^ (r & 7)) << 4));
            }
            uint32_t bfr[2][4];
            #pragma unroll
            for (int nb = 0; nb < 2; nb++) {
                int g8 = lane >> 3;
                int r  = wn * 32 + nb * 16 + ((g8 & 2) ? 8 : 0) + (lane & 7);
                int g  = (ks >> 3) + (g8 & 1);
                ldm4(bfr[nb], stB + r * 128 + ((g ^ (r & 7)) << 4));
            }
            #pragma unroll
            for (int mi = 0; mi < 4; mi++)
                #pragma unroll
                for (int ni = 0; ni < 4; ni++)
                    mma16816(acc[mi][ni], af[mi],
                             bfr[ni >> 1][(ni & 1) * 2],
                             bfr[ni >> 1][(ni & 1) * 2 + 1]);
        }
    };

    for (int it = 0; it < GK_ITERS; it += 3) {
        int s0    = it % STAGES;               // slots s0, s0+1, s0+2 (same trip)
        int phase = (it / STAGES) & 1;

        compute_stage(s0,     phase);
        compute_stage(s0 + 1, phase);
        compute_stage(s0 + 2, phase);

        __syncthreads();                       // all reads of the 3 slots done
        if (tid == 0) {                        // refill freed slots
            #pragma unroll
            for (int q = 0; q < 3; q++) {
                int ld = it + q + STAGES;
                if (ld < GK_ITERS) {
                    int s = s0 + q;
                    uint32_t sb = sbase + s * STAGE_B;
                    uint32_t fb = smem_u32(&bar_full[s]);
                    mbar_expect_tx(fb, STAGE_B);
                    bulkcp(sb,          Rb + abase + (size_t)ld * TILE_B, TILE_B, fb);
                    bulkcp(sb + TILE_B, Rb + bbase + (size_t)ld * TILE_B, TILE_B, fb);
                }
            }
        }
    }

    // Epilogue: write partial S at (bi,bj) AND its transpose at (bj,bi).
    // Diagonal tiles double-write identical values (benign).
    float* Sc = g_S[chunk];
    int rowbase = bi * TILE + wm * 64;
    int colbase = bj * TILE + wn * 32;
    #pragma unroll
    for (int mi = 0; mi < 4; mi++) {
        int r0 = rowbase + mi * 16 + (lane >> 2);
        #pragma unroll
        for (int ni = 0; ni < 4; ni++) {
            int c0 = colbase + ni * 8 + (lane & 3) * 2;
            *(float2*)&Sc[(size_t)r0 * N + c0]       = make_float2(acc[mi][ni][0], acc[mi][ni][1]);
            *(float2*)&Sc[(size_t)(r0 + 8) * N + c0] = make_float2(acc[mi][ni][2], acc[mi][ni][3]);
            Sc[(size_t)c0 * N + r0]           = acc[mi][ni][0];
            Sc[(size_t)(c0 + 1) * N + r0]     = acc[mi][ni][1];
            Sc[(size_t)c0 * N + r0 + 8]       = acc[mi][ni][2];
            Sc[(size_t)(c0 + 1) * N + r0 + 8] = acc[mi][ni][3];
        }
    }
}

// ---------------------------------------------------------------------------
// K3 (fused mine+loss): dist_ij = 0.5 - S_ij * rcp[O_ij] where O is an exact
// integer 0..8 and rcp[k] = 1/(2(k+1)) (smem table — no per-element fdiv).
// S fully materialized -> all reads row-coalesced. Parallel dtype detection.
// Last block (ticket) reduces the loss and resets the ticket.
// ---------------------------------------------------------------------------
#define MINE_T 256
__global__ void mine_kernel(const float* __restrict__ plab,
                            const void* __restrict__ glab_raw,
                            float* __restrict__ out) {
    int i = blockIdx.x;
    int t = threadIdx.x;   // MINE_T

    __shared__ int   slab[N];
    __shared__ float rcp_tab[16];

    // Parallel int64-vs-int32 detection: all odd 32-bit words zero <=> int64.
    const unsigned* w = (const unsigned*)glab_raw;
    unsigned oacc = 0;
    for (int q = 2 * t + 1; q < 2 * N; q += 2 * MINE_T) oacc |= w[q];
    int is64 = !__syncthreads_or((int)(oacc != 0));

    if (is64) {
        const long long* g64 = (const long long*)glab_raw;
        for (int j = t; j < N; j += MINE_T) slab[j] = (int)g64[j];
    } else {
        const int* g32 = (const int*)glab_raw;
        for (int j = t; j < N; j += MINE_T) slab[j] = g32[j];
    }
    if (t < 16) rcp_tab[t] = 1.0f / (2.0f * (t + 1));
    __syncthreads();

    int gi = slab[i];
    float Li[8];
    #pragma unroll
    for (int p = 0; p < 8; p++) Li[p] = plab[i * 8 + p];

    const float* S0 = &g_S[0][(size_t)i * N];
    const float* S1 = &g_S[1][(size_t)i * N];
    const float* S2 = &g_S[2][(size_t)i * N];
    const float* S3 = &g_S[3][(size_t)i * N];

    float mx = -3.4e38f, mn = 3.4e38f;
    #pragma unroll
    for (int jj = 0; jj < N / MINE_T; jj++) {
        int j = jj * MINE_T + t;
        float S = S0[j] + S1[j] + S2[j] + S3[j];
        const float4* Lj4 = (const float4*)&plab[j * 8];
        float4 a = Lj4[0], b = Lj4[1];
        float O = Li[0]*a.x + Li[1]*a.y + Li[2]*a.z + Li[3]*a.w
                + Li[4]*b.x + Li[5]*b.y + Li[6]*b.z + Li[7]*b.w;
        int k = __float2int_rn(O);
        float dist = 0.5f - S * rcp_tab[k];
        if (slab[j] == gi) mx = fmaxf(mx, dist);
        else               mn = fminf(mn, dist);
    }
    #pragma unroll
    for (int o = 16; o > 0; o >>= 1) {
        mx = fmaxf(mx, __shfl_xor_sync(0xffffffffu, mx, o));
        mn = fminf(mn, __shfl_xor_sync(0xffffffffu, mn, o));
    }
    __shared__ float smx[8], smn[8];
    __shared__ int   last_s;
    if ((t & 31) == 0) { smx[t >> 5] = mx; smn[t >> 5] = mn; }
    __syncthreads();
    if (t == 0) {
        #pragma unroll
        for (int ww = 1; ww < 8; ww++) {
            smx[0] = fmaxf(smx[0], smx[ww]);
            smn[0] = fminf(smn[0], smn[ww]);
        }
        g_ap[i] = smx[0];
        g_an[i] = smn[0];
        __threadfence();
        last_s = (atomicAdd(&g_ticket, 1) == N - 1);
    }
    __syncthreads();
    if (last_s) {
        float s = 0.f;
        for (int j = t; j < N; j += MINE_T)
            s += fmaxf(g_ap[j] - g_an[j] + MARGIN, 0.f);
        #pragma unroll
        for (int o = 16; o > 0; o >>= 1) s += __shfl_xor_sync(0xffffffffu, s, o);
        __shared__ float ws[8];
        if ((t & 31) == 0) ws[t >> 5] = s;
        __syncthreads();
        if (t == 0) {
            float tot = 0.f;
            #pragma unroll
            for (int ww = 0; ww < 8; ww++) tot += ws[ww];
            out[0] = tot / (float)N;
            g_ticket = 0;            // reset for next (graph-replayed) launch
        }
    }
}

// ---------------------------------------------------------------------------
extern "C" void kernel_launch(void* const* d_in, const int* in_sizes, int n_in,
                              void* d_out, int out_size) {
    const float* gfeat = (const float*)d_in[0];      // [1024, 2048]
    const float* pfeat = (const float*)d_in[1];      // [1024, 8, 2048]
    const float* plab  = (const float*)d_in[2];      // [1024, 8]
    const void*  glab  = d_in[3];                    // [1024] int32 or int64

    static bool attr_set = false;
    if (!attr_set) {
        cudaFuncSetAttribute(gemm_kernel,
                             cudaFuncAttributeMaxDynamicSharedMemorySize,
                             STAGES * STAGE_B + 1024);
        attr_set = true;
    }

    pack_kernel<<<N * SEGS, 256>>>(gfeat, pfeat, plab);
    gemm_kernel<<<NPAIRS * KSPLIT, 256, STAGES * STAGE_B + 1024>>>();
    mine_kernel<<<N, MINE_T>>>(plab, glab, (float*)d_out);
}